// round 6
// baseline (speedup 1.0000x reference)
#include <cuda_runtime.h>

#define DD 512
#define NN 128
#define TPB 512
#define BB 16
#define NBLK (DD / BB)
#define TINYF 1e-30f

// ---- packed f32x2 helpers (Blackwell FFMA2) ----
__device__ __forceinline__ unsigned long long fma2(unsigned long long a,
                                                   unsigned long long b,
                                                   unsigned long long c) {
    unsigned long long d;
    asm("fma.rn.f32x2 %0, %1, %2, %3;" : "=l"(d) : "l"(a), "l"(b), "l"(c));
    return d;
}
__device__ __forceinline__ float lo2(unsigned long long v) {
    return __uint_as_float((unsigned)v);
}
__device__ __forceinline__ float hi2(unsigned long long v) {
    return __uint_as_float((unsigned)(v >> 32));
}
__device__ __forceinline__ unsigned long long pack2(float x, float y) {
    unsigned long long d;
    asm("mov.b64 %0, {%1, %2};" : "=l"(d) : "f"(x), "f"(y));
    return d;
}

// Blocked Woodbury sampler, block size b=16.
//
// Per block (steps j = 0..15, global i = I0+j):
//   phase1: Y = B * UP_blk           (decision-independent GEMM)
//   phase2: G[j][m] = up_j . y_m     (16x16 small GEMM)
//   warp-0 recursion (b-dim scalars only):
//     f_{jl} = G_j . t_l ;  red_j = G_jj + sum_{l<j} piv_l f_{jl}^2
//     t_j = e_j + sum_{l<j} piv_l f_{jl} t_l ;  decision -> piv_j, outputs
//   phaseQ: Q = Y * T  (q_j columns)
//   phase4: B += Q diag(piv) Q^T     (rank-16 fold)
//
// Thread t: row r = t>>2, col slice [32h, 32h+32), h = t&3, as 16 packed
// f32x2 registers. The 4 slice-threads of a row sit in the SAME warp, so the
// Y reduction is 2 shfls (no SMEM round-trip, no barrier).
__global__ __launch_bounds__(TPB, 1)
void slater_sampler_kernel(const float* __restrict__ P,
                           const float* __restrict__ uin,
                           float* __restrict__ out,
                           int out_size)
{
    __shared__ __align__(16) float sh_UP[BB][NN];
    __shared__ __align__(16) float sh_Y[BB][NN];
    __shared__ __align__(16) float sh_Qt[BB][NN];
    __shared__ __align__(16) float sh_G[BB][17];   // padded: conflict-free row loads
    __shared__ __align__(16) float sh_T[BB][BB];
    __shared__ __align__(16) float sh_piv[BB];
    __shared__ __align__(16) float sh_u[NN];
    __shared__ int sh_kblk;

    const int tid  = threadIdx.x;
    const int lane = tid & 31;
    const int wid  = tid >> 5;
    const int r    = tid >> 2;      // owned row
    const int h    = tid & 3;       // col-slice id
    const int cbase = 32 * h;
    const int pos_base = NN * DD;

    // ---- init output: cond_probs = 0, positions = -1 ----
    {
        int n4 = out_size >> 2;
        float4* o4 = (float4*)out;
        for (int idx = tid; idx < n4; idx += TPB) {
            int base = idx * 4;
            float4 v;
            v.x = (base + 0 < pos_base) ? 0.0f : -1.0f;
            v.y = (base + 1 < pos_base) ? 0.0f : -1.0f;
            v.z = (base + 2 < pos_base) ? 0.0f : -1.0f;
            v.w = (base + 3 < pos_base) ? 0.0f : -1.0f;
            o4[idx] = v;
        }
        for (int idx = (n4 << 2) + tid; idx < out_size; idx += TPB)
            out[idx] = (idx < pos_base) ? 0.0f : -1.0f;
    }

    if (tid < NN) sh_u[tid] = uin[tid];
    if (tid == 0) sh_kblk = 0;

    // B slice = identity
    unsigned long long rb2[16];
#pragma unroll
    for (int m = 0; m < 16; ++m) {
        unsigned long long v = 0ULL;
        int c0 = cbase + 2 * m;
        if (c0 == r)          v = 0x000000003f800000ULL;
        else if (c0 + 1 == r) v = 0x3f80000000000000ULL;
        rb2[m] = v;
    }

    // ---- load UP block 0 (piece tid: i = tid>>5, f4 = tid&31) ----
    {
        const float4* Pg = (const float4*)P;
        ((float4*)sh_UP[tid >> 5])[tid & 31] = Pg[tid];
    }
    __syncthreads();

    const bool write_pos = (pos_base + NN) <= out_size;

    // sampler state (only warp 0's copies matter)
    float ratio = 1.0f, cumul = 0.0f;
    int   k = 0;

    float4 nextUP, nextUP0;

    for (int m = 0; m < NBLK; ++m) {
        const int I0 = m * BB;

        // ---- prefetch next UP block into registers (pieces 0..511) ----
        // threads 32..511 hold piece tid; threads 32..63 also hold piece tid-32
        if (m + 1 < NBLK) {
            const float4* Pn = (const float4*)(P + (size_t)(I0 + BB) * NN);
            if (tid >= 32) nextUP = Pn[tid];
            if (tid >= 32 && tid < 64) nextUP0 = Pn[tid - 32];
        }

        // ---- phase1: Y = B * UP ----
#pragma unroll
        for (int i = 0; i < BB; ++i) {
            const ulonglong2* u2 = (const ulonglong2*)(sh_UP[i] + cbase);
            unsigned long long a0 = 0, a1 = 0;
#pragma unroll
            for (int c = 0; c < 8; ++c) {
                ulonglong2 uv = u2[c];
                a0 = fma2(rb2[2 * c],     uv.x, a0);
                a1 = fma2(rb2[2 * c + 1], uv.y, a1);
            }
            float yp = (lo2(a0) + hi2(a0)) + (lo2(a1) + hi2(a1));
            yp += __shfl_xor_sync(0xffffffffu, yp, 1);
            yp += __shfl_xor_sync(0xffffffffu, yp, 2);
            if (h == 0) sh_Y[i][r] = yp;
        }
        __syncthreads();   // B1: Y ready

        // ---- phase2: G[i][l] = up_i . y_l (2 threads per entry) ----
        {
            int pr = tid >> 1;             // 0..255
            int gi = pr >> 4, gl = pr & 15;
            int half = tid & 1;
            const ulonglong2* ya = (const ulonglong2*)(sh_Y[gl]        + 64 * half);
            const ulonglong2* ua = (const ulonglong2*)(sh_UP[gi]       + 64 * half);
            unsigned long long a0 = 0, a1 = 0;
#pragma unroll
            for (int c = 0; c < 16; ++c) {
                ulonglong2 yv = ya[c], uv = ua[c];
                a0 = fma2(yv.x, uv.x, a0);
                a1 = fma2(yv.y, uv.y, a1);
            }
            float g = (lo2(a0) + hi2(a0)) + (lo2(a1) + hi2(a1));
            g += __shfl_xor_sync(0xffffffffu, g, 1);
            if (half == 0) sh_G[gi][gl] = g;
        }
        __syncthreads();   // B2: G ready

        if (wid == 0) {
            // ---- warp-0 scalar recursion over the block ----
            const int li = lane & 15;
            float Grow[BB];
#pragma unroll
            for (int l = 0; l < BB; ++l) Grow[l] = sh_G[li][l];
            float tacc[BB];
#pragma unroll
            for (int l = 0; l < BB; ++l) tacc[l] = 0.0f;
            float acc = 0.0f;

#pragma unroll
            for (int j = 0; j < BB; ++j) {
                float red = __shfl_sync(0xffffffffu, Grow[j] + acc, j);
                int iglob = I0 + j;
                bool active = (k < NN);
                float s = 1.0f - red;
                int last_allowed = DD - NN + k;
                float p  = -(s - 1.0f) * ratio;
                float uk = sh_u[k < NN ? k : NN - 1];
                bool occupy = active &&
                              (((cumul + p) >= uk) || (iglob == last_allowed));
                float pivot = occupy ? (s - 1.0f) : s;
                if (fabsf(pivot) < TINYF) pivot = TINYF;
                float pivinv = active ? (1.0f / pivot) : 0.0f;

                if (lane == 0) {
                    if (active) out[k * DD + iglob] = p;
                    if (occupy && write_pos) out[pos_base + k] = (float)iglob;
                    sh_piv[j] = pivinv;
                }
                if (occupy)      { ratio = 1.0f; cumul = 0.0f; ++k; }
                else if (active) { ratio *= s;  cumul += p; }

                // broadcast t_j = e_j + tacc_j (from lane j)
                float tj[BB];
#pragma unroll
                for (int l = 0; l < BB; ++l) {
                    float v = __shfl_sync(0xffffffffu, tacc[l], j);
                    tj[l] = v + ((l == j) ? 1.0f : 0.0f);
                }
                // store T row j (lane li writes element li via select)
                if (lane < BB) {
                    float tv = 0.0f;
#pragma unroll
                    for (int l = 0; l < BB; ++l)
                        if (l == li) tv = tj[l];
                    sh_T[j][li] = tv;
                }
                // f = Grow . tj  (pairwise tree)
                float m0 = Grow[0]  * tj[0]  + Grow[1]  * tj[1];
                float m1 = Grow[2]  * tj[2]  + Grow[3]  * tj[3];
                float m2 = Grow[4]  * tj[4]  + Grow[5]  * tj[5];
                float m3 = Grow[6]  * tj[6]  + Grow[7]  * tj[7];
                float m4 = Grow[8]  * tj[8]  + Grow[9]  * tj[9];
                float m5 = Grow[10] * tj[10] + Grow[11] * tj[11];
                float m6 = Grow[12] * tj[12] + Grow[13] * tj[13];
                float m7 = Grow[14] * tj[14] + Grow[15] * tj[15];
                float f = ((m0 + m1) + (m2 + m3)) + ((m4 + m5) + (m6 + m7));

                float pf = pivinv * f;
                acc += pf * f;
#pragma unroll
                for (int l = 0; l < BB; ++l) tacc[l] += pf * tj[l];
            }
            if (lane == 0) sh_kblk = k;
        } else {
            // ---- warps 1..15: stage next UP block (overlaps recursion) ----
            if (m + 1 < NBLK) {
                ((float4*)sh_UP[tid >> 5])[tid & 31] = nextUP;
                if (tid < 64) {
                    int p0 = tid - 32;
                    ((float4*)sh_UP[p0 >> 5])[p0 & 31] = nextUP0;
                }
            }
        }
        __syncthreads();   // B3: T/piv/kblk ready; next UP staged

        if (sh_kblk == NN) break;   // all 128 particles placed; B is dead

        // ---- phaseQ: Q[j][r] = sum_l T[j][l] * Y[l][r] ----
        {
            int qj = tid >> 5, r4 = tid & 31;
            float4 a = make_float4(0.f, 0.f, 0.f, 0.f);
#pragma unroll
            for (int l = 0; l < BB; ++l) {
                float t = sh_T[qj][l];
                float4 yv = ((const float4*)sh_Y[l])[r4];
                a.x += t * yv.x; a.y += t * yv.y;
                a.z += t * yv.z; a.w += t * yv.w;
            }
            ((float4*)sh_Qt[qj])[r4] = a;
        }
        __syncthreads();   // B4: Q ready

        // ---- phase4: B += Q diag(piv) Q^T ----
#pragma unroll
        for (int j = 0; j < BB; ++j) {
            float qs = sh_Qt[j][r] * sh_piv[j];
            unsigned long long s2 = pack2(qs, qs);
            const ulonglong2* q2 = (const ulonglong2*)(sh_Qt[j] + cbase);
#pragma unroll
            for (int c = 0; c < 8; ++c) {
                ulonglong2 qv = q2[c];
                rb2[2 * c]     = fma2(s2, qv.x, rb2[2 * c]);
                rb2[2 * c + 1] = fma2(s2, qv.y, rb2[2 * c + 1]);
            }
        }
        // no end barrier needed: next phase1 touches sh_Y/sh_UP only, which
        // no thread still reads/writes here (phase4 reads sh_Qt/sh_piv only).
    }
}

extern "C" void kernel_launch(void* const* d_in, const int* in_sizes, int n_in,
                              void* d_out, int out_size)
{
    const float* P = (const float*)d_in[0];   // (512, 128) row-major
    const float* u = (const float*)d_in[1];   // (128,)
    float* out = (float*)d_out;
    slater_sampler_kernel<<<1, TPB>>>(P, u, out, out_size);
}